// round 7
// baseline (speedup 1.0000x reference)
#include <cuda_runtime.h>
#include <cuda_bf16.h>
#include <cstdint>

#define N_NODES 100000
#define N_EDGES 3200000
#define N_FEAT 128
#define HIDDEN 64
#define N_CLASSES 3
#define N_GRAPHS 512
#define BN_EPS 1e-5f

// ---------------- scratch: device globals, accessed ONLY by symbol inside
// ---------------- device code. NEVER passed as kernel arguments (host-side
// ---------------- symbol decay gives the host shadow address; on GB300 HMM
// ---------------- that silently reads/writes host memory -> R2-R6 bug).
__device__ float g_hs[(size_t)N_NODES * HIDDEN];    // (X@W) * dinv[row]
__device__ float g_acc[(size_t)N_NODES * HIDDEN];   // edge scatter accumulator
__device__ float g_h1[(size_t)N_NODES * HIDDEN];    // layer output (post BN+ReLU)
__device__ float g_dinv[N_NODES];
__device__ int   g_deg[N_NODES];
__device__ float g_pool[N_GRAPHS * HIDDEN];
__device__ int   g_cnt[N_GRAPHS];
__device__ int   g_e64;                              // edges are int64?
__device__ int   g_b64;                              // batch is int64?
__device__ const float* g_prm[10];  // [b1,g1,bt1,rm1,rv1, b2,g2,bt2,rm2,rv2]

// ---------------- dtype detection (blocked [2,E] layout assumed; C-order) ----
// int64 data: odd 32-bit words are high halves of values < 2^31 -> all zero.
// int32 data: odd words are real indices -> ~never all zero over 64 probes.
__global__ void detect_kernel(const int* __restrict__ ew,
                              const int* __restrict__ bw) {
    int ez = 1;
    for (int i = 0; i < 64; i++)
        if (ew[2 * i + 1] != 0) ez = 0;
    g_e64 = ez;
    // probe mid-array so int32 batch values (~graph 256) are nonzero
    int bz = 1;
    for (int i = 0; i < 64; i++)
        if (bw[50000 + 2 * i + 1] != 0) bz = 0;
    g_b64 = bz;
}

__device__ __forceinline__ int e_src(const void* e, int i, int f64) {
    return f64 ? (int)((const long long*)e)[i] : ((const int*)e)[i];
}
__device__ __forceinline__ int e_dst(const void* e, int i, int f64) {
    return f64 ? (int)((const long long*)e)[(size_t)N_EDGES + i]
               : ((const int*)e)[(size_t)N_EDGES + i];
}
__device__ __forceinline__ int b_at(const void* b, int i, int f64) {
    return f64 ? (int)((const long long*)b)[i] : ((const int*)b)[i];
}

// ---------------- param classification (content-based, order-proof) ---------
// zeros: b/bt (4). ones: gamma (2). any-negative: rmean (2). else: rvar (2).
__global__ void classify_kernel(const float* p0, const float* p1,
                                const float* p2, const float* p3,
                                const float* p4, const float* p5,
                                const float* p6, const float* p7,
                                const float* p8, const float* p9) {
    const float* ps[10] = {p0, p1, p2, p3, p4, p5, p6, p7, p8, p9};
    const float* bucket[4][4];
    int cnt[4] = {0, 0, 0, 0};
    for (int i = 0; i < 10; i++) {
        bool allz = true, allo = true, anyneg = false;
        for (int k = 0; k < 64; k++) {
            float v = ps[i][k];
            allz = allz && (v == 0.0f);
            allo = allo && (v == 1.0f);
            anyneg = anyneg || (v < 0.0f);
        }
        int t = allz ? 0 : (allo ? 1 : (anyneg ? 2 : 3));
        if (cnt[t] < 4) bucket[t][cnt[t]++] = ps[i];
    }
    if (cnt[0] == 4 && cnt[1] == 2 && cnt[2] == 2 && cnt[3] == 2) {
        g_prm[0] = bucket[0][0]; g_prm[2] = bucket[0][1];   // b1, bt1
        g_prm[5] = bucket[0][2]; g_prm[7] = bucket[0][3];   // b2, bt2
        g_prm[1] = bucket[1][0]; g_prm[6] = bucket[1][1];   // g1, g2
        g_prm[3] = bucket[2][0]; g_prm[8] = bucket[2][1];   // rm1, rm2
        g_prm[4] = bucket[3][0]; g_prm[9] = bucket[3][1];   // rv1, rv2
    } else {
        for (int i = 0; i < 10; i++) g_prm[i] = ps[i];      // dict order
    }
}

// ---------------- zero ------------------------------------------------------
__global__ void zero_kernel(float* __restrict__ out, int out_size) {
    int i = blockIdx.x * blockDim.x + threadIdx.x;
    if (i < (N_NODES * HIDDEN) / 4)
        ((float4*)g_acc)[i] = make_float4(0.f, 0.f, 0.f, 0.f);
    if (i < N_NODES) g_deg[i] = 0;
    if (i < (N_GRAPHS * HIDDEN) / 4)
        ((float4*)g_pool)[i] = make_float4(0.f, 0.f, 0.f, 0.f);
    if (i < N_GRAPHS) g_cnt[i] = 0;
    if (i < out_size) out[i] = 0.f;
}

// ---------------- degree / dinv ---------------------------------------------
__global__ void deg_kernel(const void* __restrict__ edge) {
    int e = blockIdx.x * blockDim.x + threadIdx.x;
    int f = g_e64;
    if (e < N_EDGES) atomicAdd(&g_deg[e_dst(edge, e, f)], 1);
}

__global__ void dinv_kernel() {
    int i = blockIdx.x * blockDim.x + threadIdx.x;
    if (i < N_NODES) g_dinv[i] = rsqrtf((float)(g_deg[i] + 1));  // +1 self loop
}

// ---------------- GEMM: g_hs = (X[N,K] @ W[K,64]) * dinv[row] ---------------
// SRC_H1: read input from g_h1 (layer 2) instead of the X argument.
template <int K, bool SRC_H1>
__global__ void gemm_scale_kernel(const float* __restrict__ X,
                                  const float* __restrict__ W) {
    __shared__ float xs[64][68];
    __shared__ float ws[64][64];

    const float* Xp = SRC_H1 ? (const float*)g_h1 : X;
    const int t = threadIdx.x;
    const int row0 = blockIdx.x * 64;
    const int tx = t & 15;
    const int ty = t >> 4;
    const int c0 = tx * 4;
    const int r0 = ty * 4;

    float acc[4][4] = {};

    for (int kb = 0; kb < K; kb += 64) {
        for (int i = t; i < 64 * 16; i += 256) {
            int r = i >> 4, c4 = i & 15;
            *(float4*)&ws[r][c4 * 4] =
                *(const float4*)(W + (size_t)(kb + r) * 64 + c4 * 4);
        }
        for (int i = t; i < 64 * 16; i += 256) {
            int r = i >> 4, c4 = i & 15;
            int gr = row0 + r;
            float4 v = make_float4(0.f, 0.f, 0.f, 0.f);
            if (gr < N_NODES)
                v = *(const float4*)(Xp + (size_t)gr * K + kb + c4 * 4);
            *(float4*)&xs[r][c4 * 4] = v;
        }
        __syncthreads();

        #pragma unroll
        for (int k = 0; k < 64; k++) {
            float4 w4 = *(float4*)&ws[k][c0];
            #pragma unroll
            for (int i = 0; i < 4; i++) {
                float xv = xs[r0 + i][k];
                acc[i][0] += xv * w4.x;
                acc[i][1] += xv * w4.y;
                acc[i][2] += xv * w4.z;
                acc[i][3] += xv * w4.w;
            }
        }
        __syncthreads();
    }

    #pragma unroll
    for (int i = 0; i < 4; i++) {
        int gr = row0 + r0 + i;
        if (gr < N_NODES) {
            float s = g_dinv[gr];
            float4 v = make_float4(acc[i][0] * s, acc[i][1] * s,
                                   acc[i][2] * s, acc[i][3] * s);
            *(float4*)(g_hs + (size_t)gr * HIDDEN + c0) = v;
        }
    }
}

// ---------------- edge scatter: g_acc[d] += g_hs[s] -------------------------
// 16 threads/edge, float4 vector atomics (sm_90+ RED.128).
__global__ void scatter_kernel(const void* __restrict__ edge) {
    int gid = blockIdx.x * blockDim.x + threadIdx.x;
    int e = gid >> 4;
    int p = gid & 15;
    if (e >= N_EDGES) return;
    int f = g_e64;
    int s = e_src(edge, e, f);
    int d = e_dst(edge, e, f);
    float4 v = ((const float4*)(g_hs + (size_t)s * HIDDEN))[p];
    atomicAdd(((float4*)(g_acc + (size_t)d * HIDDEN)) + p, v);
}

// ---------------- combine: BN(eval)+ReLU -> g_h1 ----------------------------
// out[i,c] = relu( bn( dinv[i]*(acc[i,c]+hs[i,c]) + b[c] ) )
__global__ void combine_kernel(int layer, int resetAcc) {
    const float* b     = g_prm[layer * 5 + 0];
    const float* gamma = g_prm[layer * 5 + 1];
    const float* beta  = g_prm[layer * 5 + 2];
    const float* rmean = g_prm[layer * 5 + 3];
    const float* rvar  = g_prm[layer * 5 + 4];
    int idx = blockIdx.x * blockDim.x + threadIdx.x;
    if (idx >= N_NODES * HIDDEN) return;
    int i = idx >> 6;
    int c = idx & 63;
    float val = g_dinv[i] * (g_acc[idx] + g_hs[idx]) + __ldg(&b[c]);
    float scale = __ldg(&gamma[c]) * rsqrtf(__ldg(&rvar[c]) + BN_EPS);
    float shift = __ldg(&beta[c]) - __ldg(&rmean[c]) * scale;
    g_h1[idx] = fmaxf(val * scale + shift, 0.f);
    if (resetAcc) g_acc[idx] = 0.f;
}

// ---------------- sort-free pooling -----------------------------------------
__global__ void pool_cnt_kernel(const void* __restrict__ batch) {
    int n = blockIdx.x * blockDim.x + threadIdx.x;
    int f = g_b64;
    if (n < N_NODES) atomicAdd(&g_cnt[b_at(batch, n, f)], 1);
}

__global__ void pool_accum_kernel(const void* __restrict__ batch) {
    int gid = blockIdx.x * blockDim.x + threadIdx.x;
    int n = gid >> 4;
    int p = gid & 15;
    if (n >= N_NODES) return;
    int g = b_at(batch, n, g_b64);
    float4 v = ((const float4*)(g_h1 + (size_t)n * HIDDEN))[p];
    atomicAdd(((float4*)(g_pool + (size_t)g * HIDDEN)) + p, v);
}

__global__ void classify_out_kernel(const float* __restrict__ Wc,
                                    const float* __restrict__ bc,
                                    float* __restrict__ out) {
    int g = blockIdx.x;
    int c = threadIdx.x;   // 64 threads
    float pooled = g_pool[g * HIDDEN + c] / fmaxf((float)g_cnt[g], 1.f);
    __shared__ float sp[HIDDEN];
    sp[c] = pooled;
    __syncthreads();
    if (c < N_CLASSES) {
        float o = __ldg(&bc[c]);
        for (int k = 0; k < HIDDEN; k++)
            o += sp[k] * __ldg(&Wc[k * N_CLASSES + c]);
        out[g * N_CLASSES + c] = o;
    }
}

// ---------------- launch ----------------------------------------------------
extern "C" void kernel_launch(void* const* d_in, const int* in_sizes, int n_in,
                              void* d_out, int out_size) {
    const float *x = 0, *W1 = 0, *W2 = 0, *Wc = 0, *bc = 0;
    const void *edge = 0, *batch = 0;
    const float* v64[10] = {0};
    int n64 = 0;
    for (int i = 0; i < n_in; i++) {
        switch (in_sizes[i]) {
            case 12800000: x     = (const float*)d_in[i]; break;
            case 8192:     W1    = (const float*)d_in[i]; break;
            case 4096:     W2    = (const float*)d_in[i]; break;
            case 192:      Wc    = (const float*)d_in[i]; break;
            case 3:        bc    = (const float*)d_in[i]; break;
            case 6400000:  edge  = d_in[i];               break;
            case 100000:   batch = d_in[i];               break;
            case 64: if (n64 < 10) v64[n64++] = (const float*)d_in[i]; break;
            default: break;
        }
    }
    float* out = (float*)d_out;
    const int T = 256;

    detect_kernel<<<1, 1>>>((const int*)edge, (const int*)batch);
    classify_kernel<<<1, 1>>>(v64[0], v64[1], v64[2], v64[3], v64[4],
                              v64[5], v64[6], v64[7], v64[8], v64[9]);
    zero_kernel<<<((N_NODES * HIDDEN / 4) + T - 1) / T, T>>>(out, out_size);
    deg_kernel<<<(N_EDGES + T - 1) / T, T>>>(edge);
    dinv_kernel<<<(N_NODES + T - 1) / T, T>>>();

    // layer 1
    gemm_scale_kernel<N_FEAT, false><<<(N_NODES + 63) / 64, T>>>(x, W1);
    scatter_kernel<<<(N_EDGES * 16) / T, T>>>(edge);
    combine_kernel<<<(N_NODES * HIDDEN + T - 1) / T, T>>>(0, 1);

    // layer 2
    gemm_scale_kernel<HIDDEN, true><<<(N_NODES + 63) / 64, T>>>(0, W2);
    scatter_kernel<<<(N_EDGES * 16) / T, T>>>(edge);
    combine_kernel<<<(N_NODES * HIDDEN + T - 1) / T, T>>>(1, 0);

    // pool + classifier
    pool_cnt_kernel<<<(N_NODES + T - 1) / T, T>>>(batch);
    pool_accum_kernel<<<(N_NODES * 16 + T - 1) / T, T>>>(batch);
    classify_out_kernel<<<N_GRAPHS, HIDDEN>>>(Wc, bc, out);
}

// round 8
// speedup vs baseline: 1.1231x; 1.1231x over previous
#include <cuda_runtime.h>
#include <cuda_bf16.h>
#include <cstdint>

#define N_NODES 100000
#define N_EDGES 3200000
#define N_FEAT 128
#define HIDDEN 64
#define N_CLASSES 3
#define N_GRAPHS 512
#define BN_EPS 1e-5f
#define SCAN_T 1024
#define CHUNK ((N_NODES + SCAN_T - 1) / SCAN_T)

// ---- scratch: device globals, accessed ONLY by symbol in device code -------
__device__ float g_hs[(size_t)N_NODES * HIDDEN];    // (X@W) * dinv[row]
__device__ float g_h1[(size_t)N_NODES * HIDDEN];    // layer-1 output
__device__ float g_dinv[N_NODES];
__device__ int   g_deg[N_NODES];
__device__ int   g_row[N_NODES + 1];                // CSR row offsets (by dst)
__device__ int   g_cur[N_NODES];                    // fill cursors
__device__ int   g_csr[N_EDGES];                    // src list grouped by dst
__device__ float g_pool[N_GRAPHS * HIDDEN];
__device__ int   g_cnt[N_GRAPHS];
__device__ int   g_e64, g_b64;
__device__ const float* g_prm[10];  // [b1,g1,bt1,rm1,rv1, b2,g2,bt2,rm2,rv2]
__device__ float g_A[2 * HIDDEN];   // BN scale per layer/channel
__device__ float g_C[2 * HIDDEN];   // BN shift (bias folded)

// ---- dtype detection (blocked [2,E] layout, C-order) -----------------------
__global__ void detect_kernel(const int* __restrict__ ew,
                              const int* __restrict__ bw) {
    int ez = 1;
    for (int i = 0; i < 64; i++)
        if (ew[2 * i + 1] != 0) ez = 0;
    g_e64 = ez;
    int bz = 1;
    for (int i = 0; i < 64; i++)
        if (bw[50000 + 2 * i + 1] != 0) bz = 0;
    g_b64 = bz;
}

__device__ __forceinline__ int e_src(const void* e, int i, int f64) {
    return f64 ? (int)((const long long*)e)[i] : ((const int*)e)[i];
}
__device__ __forceinline__ int e_dst(const void* e, int i, int f64) {
    return f64 ? (int)((const long long*)e)[(size_t)N_EDGES + i]
               : ((const int*)e)[(size_t)N_EDGES + i];
}
__device__ __forceinline__ int b_at(const void* b, int i, int f64) {
    return f64 ? (int)((const long long*)b)[i] : ((const int*)b)[i];
}

// ---- param classification + BN coefficient precompute ----------------------
__global__ void classify_kernel(const float* p0, const float* p1,
                                const float* p2, const float* p3,
                                const float* p4, const float* p5,
                                const float* p6, const float* p7,
                                const float* p8, const float* p9) {
    const float* ps[10] = {p0, p1, p2, p3, p4, p5, p6, p7, p8, p9};
    const float* bucket[4][4];
    int cnt[4] = {0, 0, 0, 0};
    for (int i = 0; i < 10; i++) {
        bool allz = true, allo = true, anyneg = false;
        for (int k = 0; k < 64; k++) {
            float v = ps[i][k];
            allz = allz && (v == 0.0f);
            allo = allo && (v == 1.0f);
            anyneg = anyneg || (v < 0.0f);
        }
        int t = allz ? 0 : (allo ? 1 : (anyneg ? 2 : 3));
        if (cnt[t] < 4) bucket[t][cnt[t]++] = ps[i];
    }
    if (cnt[0] == 4 && cnt[1] == 2 && cnt[2] == 2 && cnt[3] == 2) {
        g_prm[0] = bucket[0][0]; g_prm[2] = bucket[0][1];
        g_prm[5] = bucket[0][2]; g_prm[7] = bucket[0][3];
        g_prm[1] = bucket[1][0]; g_prm[6] = bucket[1][1];
        g_prm[3] = bucket[2][0]; g_prm[8] = bucket[2][1];
        g_prm[4] = bucket[3][0]; g_prm[9] = bucket[3][1];
    } else {
        for (int i = 0; i < 10; i++) g_prm[i] = ps[i];
    }
    // fold BN (eval) + bias: out = relu(dinv*sum*A + C)
    for (int L = 0; L < 2; L++) {
        const float* b     = g_prm[L * 5 + 0];
        const float* gamma = g_prm[L * 5 + 1];
        const float* beta  = g_prm[L * 5 + 2];
        const float* rmean = g_prm[L * 5 + 3];
        const float* rvar  = g_prm[L * 5 + 4];
        for (int c = 0; c < 64; c++) {
            float sc = gamma[c] * rsqrtf(rvar[c] + BN_EPS);
            g_A[L * 64 + c] = sc;
            g_C[L * 64 + c] = beta[c] + (b[c] - rmean[c]) * sc;
        }
    }
}

// ---- zero ------------------------------------------------------------------
__global__ void zero_kernel(float* __restrict__ out, int out_size) {
    int i = blockIdx.x * blockDim.x + threadIdx.x;
    if (i < N_NODES) g_deg[i] = 0;
    if (i < (N_GRAPHS * HIDDEN) / 4)
        ((float4*)g_pool)[i] = make_float4(0.f, 0.f, 0.f, 0.f);
    if (i < N_GRAPHS) g_cnt[i] = 0;
    if (i < out_size) out[i] = 0.f;
}

// ---- degree ----------------------------------------------------------------
__global__ void deg_kernel(const void* __restrict__ edge) {
    int e = blockIdx.x * blockDim.x + threadIdx.x;
    int f = g_e64;
    if (e < N_EDGES) atomicAdd(&g_deg[e_dst(edge, e, f)], 1);
}

// ---- prefix scan -> row offsets, cursors, dinv (single block) --------------
__global__ void scan_kernel() {
    __shared__ int sp[SCAN_T];
    int t = threadIdx.x;
    int lo = t * CHUNK;
    int hi = lo + CHUNK < N_NODES ? lo + CHUNK : N_NODES;
    int s = 0;
    for (int i = lo; i < hi; i++) s += g_deg[i];
    sp[t] = s;
    __syncthreads();
    for (int off = 1; off < SCAN_T; off <<= 1) {
        int v = (t >= off) ? sp[t - off] : 0;
        __syncthreads();
        sp[t] += v;
        __syncthreads();
    }
    int run = (t > 0) ? sp[t - 1] : 0;
    for (int i = lo; i < hi; i++) {
        g_row[i] = run;
        g_cur[i] = run;
        int d = g_deg[i];
        run += d;
        g_dinv[i] = rsqrtf((float)(d + 1));   // +1 self loop
    }
    if (t == SCAN_T - 1) g_row[N_NODES] = run;
}

// ---- CSR fill: group src indices by dst ------------------------------------
__global__ void fill_kernel(const void* __restrict__ edge) {
    int e = blockIdx.x * blockDim.x + threadIdx.x;
    if (e >= N_EDGES) return;
    int f = g_e64;
    int s = e_src(edge, e, f);
    int d = e_dst(edge, e, f);
    int pos = atomicAdd(&g_cur[d], 1);
    g_csr[pos] = s;
}

// ---- pool counts -----------------------------------------------------------
__global__ void pool_cnt_kernel(const void* __restrict__ batch) {
    int n = blockIdx.x * blockDim.x + threadIdx.x;
    int f = g_b64;
    if (n < N_NODES) atomicAdd(&g_cnt[b_at(batch, n, f)], 1);
}

// ---- GEMM: g_hs = (X[N,K] @ W[K,64]) * dinv[row] ---------------------------
template <int K, bool SRC_H1>
__global__ void gemm_scale_kernel(const float* __restrict__ X,
                                  const float* __restrict__ W) {
    __shared__ float xs[64][68];
    __shared__ float ws[64][64];

    const float* Xp = SRC_H1 ? (const float*)g_h1 : X;
    const int t = threadIdx.x;
    const int row0 = blockIdx.x * 64;
    const int tx = t & 15;
    const int ty = t >> 4;
    const int c0 = tx * 4;
    const int r0 = ty * 4;

    float acc[4][4] = {};

    for (int kb = 0; kb < K; kb += 64) {
        for (int i = t; i < 64 * 16; i += 256) {
            int r = i >> 4, c4 = i & 15;
            *(float4*)&ws[r][c4 * 4] =
                *(const float4*)(W + (size_t)(kb + r) * 64 + c4 * 4);
        }
        for (int i = t; i < 64 * 16; i += 256) {
            int r = i >> 4, c4 = i & 15;
            int gr = row0 + r;
            float4 v = make_float4(0.f, 0.f, 0.f, 0.f);
            if (gr < N_NODES)
                v = *(const float4*)(Xp + (size_t)gr * K + kb + c4 * 4);
            *(float4*)&xs[r][c4 * 4] = v;
        }
        __syncthreads();

        #pragma unroll
        for (int k = 0; k < 64; k++) {
            float4 w4 = *(float4*)&ws[k][c0];
            #pragma unroll
            for (int i = 0; i < 4; i++) {
                float xv = xs[r0 + i][k];
                acc[i][0] += xv * w4.x;
                acc[i][1] += xv * w4.y;
                acc[i][2] += xv * w4.z;
                acc[i][3] += xv * w4.w;
            }
        }
        __syncthreads();
    }

    #pragma unroll
    for (int i = 0; i < 4; i++) {
        int gr = row0 + r0 + i;
        if (gr < N_NODES) {
            float s = g_dinv[gr];
            float4 v = make_float4(acc[i][0] * s, acc[i][1] * s,
                                   acc[i][2] * s, acc[i][3] * s);
            *(float4*)(g_hs + (size_t)gr * HIDDEN + c0) = v;
        }
    }
}

// ---- fused gather + BN + ReLU (+ pool for layer 2) -------------------------
// One warp per dst node. Half-warps walk alternate in-edges; 16 lanes x float4
// cover the 64-float row. Epilogue folds self-loop, dinv, BN, ReLU.
template <int LAYER>
__global__ void gather_kernel(const void* __restrict__ batch) {
    int node = (blockIdx.x * blockDim.x + threadIdx.x) >> 5;
    if (node >= N_NODES) return;
    int lane = threadIdx.x & 31;
    int p = lane & 15;
    int half = lane >> 4;
    int beg = g_row[node], end = g_row[node + 1];

    float4 a = make_float4(0.f, 0.f, 0.f, 0.f);
    for (int i = beg + half; i < end; i += 2) {
        int s = g_csr[i];
        float4 v = *((const float4*)(g_hs + (size_t)s * HIDDEN) + p);
        a.x += v.x; a.y += v.y; a.z += v.z; a.w += v.w;
    }
    a.x += __shfl_down_sync(0xffffffffu, a.x, 16);
    a.y += __shfl_down_sync(0xffffffffu, a.y, 16);
    a.z += __shfl_down_sync(0xffffffffu, a.z, 16);
    a.w += __shfl_down_sync(0xffffffffu, a.w, 16);

    if (half == 0) {
        float4 sv = *((const float4*)(g_hs + (size_t)node * HIDDEN) + p);
        float di = g_dinv[node];
        float4 A = *((const float4*)(g_A + LAYER * HIDDEN) + p);
        float4 C = *((const float4*)(g_C + LAYER * HIDDEN) + p);
        float4 r;
        r.x = fmaxf(di * (a.x + sv.x) * A.x + C.x, 0.f);
        r.y = fmaxf(di * (a.y + sv.y) * A.y + C.y, 0.f);
        r.z = fmaxf(di * (a.z + sv.z) * A.z + C.z, 0.f);
        r.w = fmaxf(di * (a.w + sv.w) * A.w + C.w, 0.f);
        if (LAYER == 0) {
            *((float4*)(g_h1 + (size_t)node * HIDDEN) + p) = r;
        } else {
            int g = b_at(batch, node, g_b64);
            atomicAdd((float4*)(g_pool + (size_t)g * HIDDEN) + p, r);
        }
    }
}

// ---- classifier ------------------------------------------------------------
__global__ void classify_out_kernel(const float* __restrict__ Wc,
                                    const float* __restrict__ bc,
                                    float* __restrict__ out) {
    int g = blockIdx.x;
    int c = threadIdx.x;   // 64 threads
    float pooled = g_pool[g * HIDDEN + c] / fmaxf((float)g_cnt[g], 1.f);
    __shared__ float sp[HIDDEN];
    sp[c] = pooled;
    __syncthreads();
    if (c < N_CLASSES) {
        float o = __ldg(&bc[c]);
        for (int k = 0; k < HIDDEN; k++)
            o += sp[k] * __ldg(&Wc[k * N_CLASSES + c]);
        out[g * N_CLASSES + c] = o;
    }
}

// ---- launch ----------------------------------------------------------------
extern "C" void kernel_launch(void* const* d_in, const int* in_sizes, int n_in,
                              void* d_out, int out_size) {
    const float *x = 0, *W1 = 0, *W2 = 0, *Wc = 0, *bc = 0;
    const void *edge = 0, *batch = 0;
    const float* v64[10] = {0};
    int n64 = 0;
    for (int i = 0; i < n_in; i++) {
        switch (in_sizes[i]) {
            case 12800000: x     = (const float*)d_in[i]; break;
            case 8192:     W1    = (const float*)d_in[i]; break;
            case 4096:     W2    = (const float*)d_in[i]; break;
            case 192:      Wc    = (const float*)d_in[i]; break;
            case 3:        bc    = (const float*)d_in[i]; break;
            case 6400000:  edge  = d_in[i];               break;
            case 100000:   batch = d_in[i];               break;
            case 64: if (n64 < 10) v64[n64++] = (const float*)d_in[i]; break;
            default: break;
        }
    }
    float* out = (float*)d_out;
    const int T = 256;

    detect_kernel<<<1, 1>>>((const int*)edge, (const int*)batch);
    classify_kernel<<<1, 1>>>(v64[0], v64[1], v64[2], v64[3], v64[4],
                              v64[5], v64[6], v64[7], v64[8], v64[9]);
    zero_kernel<<<(N_NODES + T - 1) / T, T>>>(out, out_size);
    deg_kernel<<<(N_EDGES + T - 1) / T, T>>>(edge);
    scan_kernel<<<1, SCAN_T>>>();
    fill_kernel<<<(N_EDGES + T - 1) / T, T>>>(edge);
    pool_cnt_kernel<<<(N_NODES + T - 1) / T, T>>>(batch);

    // layer 1: GEMM -> fused gather+BN+ReLU -> h1
    gemm_scale_kernel<N_FEAT, false><<<(N_NODES + 63) / 64, T>>>(x, W1);
    gather_kernel<0><<<(N_NODES * 32 + T - 1) / T, T>>>(batch);

    // layer 2: GEMM -> fused gather+BN+ReLU+pool
    gemm_scale_kernel<HIDDEN, true><<<(N_NODES + 63) / 64, T>>>(0, W2);
    gather_kernel<1><<<(N_NODES * 32 + T - 1) / T, T>>>(batch);

    // classifier
    classify_out_kernel<<<N_GRAPHS, HIDDEN>>>(Wc, bc, out);
}

// round 9
// speedup vs baseline: 1.1521x; 1.0259x over previous
#include <cuda_runtime.h>
#include <cuda_fp16.h>
#include <cstdint>

#define N_NODES 100000
#define N_EDGES 3200000
#define N_FEAT 128
#define HIDDEN 64
#define N_CLASSES 3
#define N_GRAPHS 512
#define BN_EPS 1e-5f
#define SCAN_T 1024
#define CHUNK ((N_NODES + SCAN_T - 1) / SCAN_T)

// ---- scratch: device globals, accessed ONLY by symbol in device code -------
__device__ __half g_hs[(size_t)N_NODES * HIDDEN];   // X@W in fp16 (unscaled)
__device__ float  g_h1[(size_t)N_NODES * HIDDEN];   // layer-1 output (fp32)
__device__ float  g_dinv[N_NODES];
__device__ int    g_deg[N_NODES];
__device__ int    g_row[N_NODES + 1];               // CSR row offsets (by dst)
__device__ int    g_cur[N_NODES];                   // fill cursors
__device__ int    g_csr[N_EDGES];                   // src list grouped by dst
__device__ float  g_pool[N_GRAPHS * HIDDEN];
__device__ int    g_cnt[N_GRAPHS];
__device__ int    g_e64, g_b64;
__device__ const float* g_prm[10];  // [b1,g1,bt1,rm1,rv1, b2,g2,bt2,rm2,rv2]
__device__ float  g_A[2 * HIDDEN];  // BN scale per layer/channel
__device__ float  g_C[2 * HIDDEN];  // BN shift (bias folded)

// ---- dtype detection (blocked [2,E] layout, C-order) -----------------------
__global__ void detect_kernel(const int* __restrict__ ew,
                              const int* __restrict__ bw) {
    int ez = 1;
    for (int i = 0; i < 64; i++)
        if (ew[2 * i + 1] != 0) ez = 0;
    g_e64 = ez;
    int bz = 1;
    for (int i = 0; i < 64; i++)
        if (bw[50000 + 2 * i + 1] != 0) bz = 0;
    g_b64 = bz;
}

__device__ __forceinline__ int e_src(const void* e, int i, int f64) {
    return f64 ? (int)((const long long*)e)[i] : ((const int*)e)[i];
}
__device__ __forceinline__ int e_dst(const void* e, int i, int f64) {
    return f64 ? (int)((const long long*)e)[(size_t)N_EDGES + i]
               : ((const int*)e)[(size_t)N_EDGES + i];
}
__device__ __forceinline__ int b_at(const void* b, int i, int f64) {
    return f64 ? (int)((const long long*)b)[i] : ((const int*)b)[i];
}

// ---- param classification + BN coefficient precompute ----------------------
__global__ void classify_kernel(const float* p0, const float* p1,
                                const float* p2, const float* p3,
                                const float* p4, const float* p5,
                                const float* p6, const float* p7,
                                const float* p8, const float* p9) {
    const float* ps[10] = {p0, p1, p2, p3, p4, p5, p6, p7, p8, p9};
    const float* bucket[4][4];
    int cnt[4] = {0, 0, 0, 0};
    for (int i = 0; i < 10; i++) {
        bool allz = true, allo = true, anyneg = false;
        for (int k = 0; k < 64; k++) {
            float v = ps[i][k];
            allz = allz && (v == 0.0f);
            allo = allo && (v == 1.0f);
            anyneg = anyneg || (v < 0.0f);
        }
        int t = allz ? 0 : (allo ? 1 : (anyneg ? 2 : 3));
        if (cnt[t] < 4) bucket[t][cnt[t]++] = ps[i];
    }
    if (cnt[0] == 4 && cnt[1] == 2 && cnt[2] == 2 && cnt[3] == 2) {
        g_prm[0] = bucket[0][0]; g_prm[2] = bucket[0][1];
        g_prm[5] = bucket[0][2]; g_prm[7] = bucket[0][3];
        g_prm[1] = bucket[1][0]; g_prm[6] = bucket[1][1];
        g_prm[3] = bucket[2][0]; g_prm[8] = bucket[2][1];
        g_prm[4] = bucket[3][0]; g_prm[9] = bucket[3][1];
    } else {
        for (int i = 0; i < 10; i++) g_prm[i] = ps[i];
    }
    for (int L = 0; L < 2; L++) {
        const float* b     = g_prm[L * 5 + 0];
        const float* gamma = g_prm[L * 5 + 1];
        const float* beta  = g_prm[L * 5 + 2];
        const float* rmean = g_prm[L * 5 + 3];
        const float* rvar  = g_prm[L * 5 + 4];
        for (int c = 0; c < 64; c++) {
            float sc = gamma[c] * rsqrtf(rvar[c] + BN_EPS);
            g_A[L * 64 + c] = sc;
            g_C[L * 64 + c] = beta[c] + (b[c] - rmean[c]) * sc;
        }
    }
}

// ---- zero ------------------------------------------------------------------
__global__ void zero_kernel(float* __restrict__ out, int out_size) {
    int i = blockIdx.x * blockDim.x + threadIdx.x;
    if (i < N_NODES) g_deg[i] = 0;
    if (i < (N_GRAPHS * HIDDEN) / 4)
        ((float4*)g_pool)[i] = make_float4(0.f, 0.f, 0.f, 0.f);
    if (i < N_GRAPHS) g_cnt[i] = 0;
    if (i < out_size) out[i] = 0.f;
}

// ---- degree ----------------------------------------------------------------
__global__ void deg_kernel(const void* __restrict__ edge) {
    int e = blockIdx.x * blockDim.x + threadIdx.x;
    int f = g_e64;
    if (e < N_EDGES) atomicAdd(&g_deg[e_dst(edge, e, f)], 1);
}

// ---- prefix scan -> row offsets, cursors, dinv (single block) --------------
__global__ void scan_kernel() {
    __shared__ int sp[SCAN_T];
    int t = threadIdx.x;
    int lo = t * CHUNK;
    int hi = lo + CHUNK < N_NODES ? lo + CHUNK : N_NODES;
    int s = 0;
    for (int i = lo; i < hi; i++) s += g_deg[i];
    sp[t] = s;
    __syncthreads();
    for (int off = 1; off < SCAN_T; off <<= 1) {
        int v = (t >= off) ? sp[t - off] : 0;
        __syncthreads();
        sp[t] += v;
        __syncthreads();
    }
    int run = (t > 0) ? sp[t - 1] : 0;
    for (int i = lo; i < hi; i++) {
        g_row[i] = run;
        g_cur[i] = run;
        int d = g_deg[i];
        run += d;
        g_dinv[i] = rsqrtf((float)(d + 1));   // +1 self loop
    }
    if (t == SCAN_T - 1) g_row[N_NODES] = run;
}

// ---- CSR fill: group src indices by dst ------------------------------------
__global__ void fill_kernel(const void* __restrict__ edge) {
    int e = blockIdx.x * blockDim.x + threadIdx.x;
    if (e >= N_EDGES) return;
    int f = g_e64;
    int s = e_src(edge, e, f);
    int d = e_dst(edge, e, f);
    int pos = atomicAdd(&g_cur[d], 1);
    g_csr[pos] = s;
}

// ---- pool counts -----------------------------------------------------------
__global__ void pool_cnt_kernel(const void* __restrict__ batch) {
    int n = blockIdx.x * blockDim.x + threadIdx.x;
    int f = g_b64;
    if (n < N_NODES) atomicAdd(&g_cnt[b_at(batch, n, f)], 1);
}

// ---- GEMM: g_hs = fp16(X[N,K] @ W[K,64])  (no dinv — applied in gather) ----
template <int K, bool SRC_H1>
__global__ void gemm_kernel(const float* __restrict__ X,
                            const float* __restrict__ W) {
    __shared__ float xs[64][68];
    __shared__ float ws[64][64];

    const float* Xp = SRC_H1 ? (const float*)g_h1 : X;
    const int t = threadIdx.x;
    const int row0 = blockIdx.x * 64;
    const int tx = t & 15;
    const int ty = t >> 4;
    const int c0 = tx * 4;
    const int r0 = ty * 4;

    float acc[4][4] = {};

    for (int kb = 0; kb < K; kb += 64) {
        for (int i = t; i < 64 * 16; i += 256) {
            int r = i >> 4, c4 = i & 15;
            *(float4*)&ws[r][c4 * 4] =
                *(const float4*)(W + (size_t)(kb + r) * 64 + c4 * 4);
        }
        for (int i = t; i < 64 * 16; i += 256) {
            int r = i >> 4, c4 = i & 15;
            int gr = row0 + r;
            float4 v = make_float4(0.f, 0.f, 0.f, 0.f);
            if (gr < N_NODES)
                v = *(const float4*)(Xp + (size_t)gr * K + kb + c4 * 4);
            *(float4*)&xs[r][c4 * 4] = v;
        }
        __syncthreads();

        #pragma unroll
        for (int k = 0; k < 64; k++) {
            float4 w4 = *(float4*)&ws[k][c0];
            #pragma unroll
            for (int i = 0; i < 4; i++) {
                float xv = xs[r0 + i][k];
                acc[i][0] += xv * w4.x;
                acc[i][1] += xv * w4.y;
                acc[i][2] += xv * w4.z;
                acc[i][3] += xv * w4.w;
            }
        }
        __syncthreads();
    }

    #pragma unroll
    for (int i = 0; i < 4; i++) {
        int gr = row0 + r0 + i;
        if (gr < N_NODES) {
            __half2 h01 = __floats2half2_rn(acc[i][0], acc[i][1]);
            __half2 h23 = __floats2half2_rn(acc[i][2], acc[i][3]);
            uint2 packed = make_uint2(*(unsigned*)&h01, *(unsigned*)&h23);
            *((uint2*)(g_hs + (size_t)gr * HIDDEN) + tx) = packed;
        }
    }
}

// ---- fused gather + norm + BN + ReLU (+ pool for layer 2) ------------------
// One warp per dst node; 2 half-warps walk alternate in-edges; 16 lanes x 8B
// (4 halves) cover the 128-byte fp16 row. acc[d,:] = dinv[d]*Σ dinv[s]*hs[s,:]
template <int LAYER>
__global__ void gather_kernel(const void* __restrict__ batch) {
    int node = (blockIdx.x * blockDim.x + threadIdx.x) >> 5;
    if (node >= N_NODES) return;
    int lane = threadIdx.x & 31;
    int p = lane & 15;
    int half = lane >> 4;
    int beg = g_row[node], end = g_row[node + 1];

    float4 a = make_float4(0.f, 0.f, 0.f, 0.f);
    for (int i = beg + half; i < end; i += 2) {
        int s = g_csr[i];
        float ds = g_dinv[s];
        uint2 raw = *((const uint2*)(g_hs + (size_t)s * HIDDEN) + p);
        float2 f01 = __half22float2(*(__half2*)&raw.x);
        float2 f23 = __half22float2(*(__half2*)&raw.y);
        a.x += ds * f01.x; a.y += ds * f01.y;
        a.z += ds * f23.x; a.w += ds * f23.y;
    }
    a.x += __shfl_down_sync(0xffffffffu, a.x, 16);
    a.y += __shfl_down_sync(0xffffffffu, a.y, 16);
    a.z += __shfl_down_sync(0xffffffffu, a.z, 16);
    a.w += __shfl_down_sync(0xffffffffu, a.w, 16);

    if (half == 0) {
        float di = g_dinv[node];
        uint2 raw = *((const uint2*)(g_hs + (size_t)node * HIDDEN) + p);
        float2 s01 = __half22float2(*(__half2*)&raw.x);
        float2 s23 = __half22float2(*(__half2*)&raw.y);
        float4 A = *((const float4*)(g_A + LAYER * HIDDEN) + p);
        float4 C = *((const float4*)(g_C + LAYER * HIDDEN) + p);
        float4 r;
        r.x = fmaxf(di * (a.x + di * s01.x) * A.x + C.x, 0.f);
        r.y = fmaxf(di * (a.y + di * s01.y) * A.y + C.y, 0.f);
        r.z = fmaxf(di * (a.z + di * s23.x) * A.z + C.z, 0.f);
        r.w = fmaxf(di * (a.w + di * s23.y) * A.w + C.w, 0.f);
        if (LAYER == 0) {
            *((float4*)(g_h1 + (size_t)node * HIDDEN) + p) = r;
        } else {
            int g = b_at(batch, node, g_b64);
            atomicAdd((float4*)(g_pool + (size_t)g * HIDDEN) + p, r);
        }
    }
}

// ---- classifier ------------------------------------------------------------
__global__ void classify_out_kernel(const float* __restrict__ Wc,
                                    const float* __restrict__ bc,
                                    float* __restrict__ out) {
    int g = blockIdx.x;
    int c = threadIdx.x;   // 64 threads
    float pooled = g_pool[g * HIDDEN + c] / fmaxf((float)g_cnt[g], 1.f);
    __shared__ float sp[HIDDEN];
    sp[c] = pooled;
    __syncthreads();
    if (c < N_CLASSES) {
        float o = __ldg(&bc[c]);
        for (int k = 0; k < HIDDEN; k++)
            o += sp[k] * __ldg(&Wc[k * N_CLASSES + c]);
        out[g * N_CLASSES + c] = o;
    }
}

// ---- launch ----------------------------------------------------------------
extern "C" void kernel_launch(void* const* d_in, const int* in_sizes, int n_in,
                              void* d_out, int out_size) {
    const float *x = 0, *W1 = 0, *W2 = 0, *Wc = 0, *bc = 0;
    const void *edge = 0, *batch = 0;
    const float* v64[10] = {0};
    int n64 = 0;
    for (int i = 0; i < n_in; i++) {
        switch (in_sizes[i]) {
            case 12800000: x     = (const float*)d_in[i]; break;
            case 8192:     W1    = (const float*)d_in[i]; break;
            case 4096:     W2    = (const float*)d_in[i]; break;
            case 192:      Wc    = (const float*)d_in[i]; break;
            case 3:        bc    = (const float*)d_in[i]; break;
            case 6400000:  edge  = d_in[i];               break;
            case 100000:   batch = d_in[i];               break;
            case 64: if (n64 < 10) v64[n64++] = (const float*)d_in[i]; break;
            default: break;
        }
    }
    float* out = (float*)d_out;
    const int T = 256;

    // fork: GEMM1 is independent of the CSR-build chain (dinv applied in gather)
    cudaStream_t s2;
    cudaStreamCreate(&s2);
    cudaEvent_t evFork, evJoin;
    cudaEventCreateWithFlags(&evFork, cudaEventDisableTiming);
    cudaEventCreateWithFlags(&evJoin, cudaEventDisableTiming);

    cudaEventRecord(evFork, 0);
    cudaStreamWaitEvent(s2, evFork, 0);
    gemm_kernel<N_FEAT, false><<<(N_NODES + 63) / 64, T, 0, s2>>>(x, W1);
    cudaEventRecord(evJoin, s2);

    // main chain: dtype + params + CSR build
    detect_kernel<<<1, 1>>>((const int*)edge, (const int*)batch);
    classify_kernel<<<1, 1>>>(v64[0], v64[1], v64[2], v64[3], v64[4],
                              v64[5], v64[6], v64[7], v64[8], v64[9]);
    zero_kernel<<<(N_NODES + T - 1) / T, T>>>(out, out_size);
    deg_kernel<<<(N_EDGES + T - 1) / T, T>>>(edge);
    scan_kernel<<<1, SCAN_T>>>();
    fill_kernel<<<(N_EDGES + T - 1) / T, T>>>(edge);
    pool_cnt_kernel<<<(N_NODES + T - 1) / T, T>>>(batch);

    // join, then layer 1 gather
    cudaStreamWaitEvent(0, evJoin, 0);
    gather_kernel<0><<<(N_NODES * 32 + T - 1) / T, T>>>(batch);

    // layer 2
    gemm_kernel<HIDDEN, true><<<(N_NODES + 63) / 64, T>>>(0, W2);
    gather_kernel<1><<<(N_NODES * 32 + T - 1) / T, T>>>(batch);

    // classifier
    classify_out_kernel<<<N_GRAPHS, HIDDEN>>>(Wc, bc, out);
}